// round 12
// baseline (speedup 1.0000x reference)
#include <cuda_runtime.h>
#include <cuda_fp16.h>
#include <cstdint>

#define DEV_INLINE __device__ __forceinline__

constexpr int B  = 4;
constexpr int C  = 64;
constexpr int CK = 8;
constexpr int N  = 4096;
constexpr int TQ = 64;   // queries per block (4 warps x 16)
constexpr int TK = 64;   // keys per tile
constexpr int NT = N / TK;
constexpr int SP = 2;    // split-K factor
constexpr int NTS = NT / SP;
constexpr float LOG2E = 1.4426950408889634f;

// fp16 scratch:
//   g_q/g_k: [b][n][c]  (8 half = 16B per n)
//   g_v:     [b][c][n]
__device__ __half g_q[B * N * CK];
__device__ __half g_k[B * N * CK];
__device__ __half g_v[B * C * N];
// split-K partials
__device__ float g_po[SP * B * C * N];   // unnormalized O
__device__ float g_m[SP * B * N];
__device__ float g_l[SP * B * N];

DEV_INLINE uint32_t pack_h2(float lo, float hi) {
    uint32_t r;
    asm("cvt.rn.f16x2.f32 %0, %1, %2;" : "=r"(r) : "f"(hi), "f"(lo));
    return r;
}
DEV_INLINE float ex2f(float x) {
    float r; asm("ex2.approx.f32 %0, %1;" : "=f"(r) : "f"(x)); return r;
}
DEV_INLINE uint32_t h2ex2(uint32_t a) {
    uint32_t d; asm("ex2.approx.f16x2 %0, %1;" : "=r"(d) : "r"(a)); return d;
}
DEV_INLINE uint32_t h2add(uint32_t a, uint32_t b) {
    uint32_t d; asm("add.rn.f16x2 %0, %1, %2;" : "=r"(d) : "r"(a), "r"(b)); return d;
}
DEV_INLINE uint32_t smem_u32(const void* p) {
    uint32_t a;
    asm("{ .reg .u64 t; cvta.to.shared.u64 t, %1; cvt.u32.u64 %0, t; }"
        : "=r"(a) : "l"(p));
    return a;
}
DEV_INLINE void cp16(uint32_t dst, const void* src) {
    asm volatile("cp.async.ca.shared.global [%0], [%1], 16;"
                 :: "r"(dst), "l"(src) : "memory");
}
#define CP_COMMIT() asm volatile("cp.async.commit_group;" ::: "memory")
#define CP_WAIT1()  asm volatile("cp.async.wait_group 1;" ::: "memory")
#define CP_WAIT0()  asm volatile("cp.async.wait_group 0;" ::: "memory")

#define MMA_K8(d, a0, a1, b0) \
    asm volatile("mma.sync.aligned.m16n8k8.row.col.f32.f16.f16.f32 " \
        "{%0,%1,%2,%3}, {%4,%5}, {%6}, {%0,%1,%2,%3};" \
        : "+f"((d)[0]), "+f"((d)[1]), "+f"((d)[2]), "+f"((d)[3]) \
        : "r"(a0), "r"(a1), "r"(b0))

#define MMA_K16(d, a0, a1, a2, a3, b0, b1) \
    asm volatile("mma.sync.aligned.m16n8k16.row.col.f32.f16.f16.f32 " \
        "{%0,%1,%2,%3}, {%4,%5,%6,%7}, {%8,%9}, {%0,%1,%2,%3};" \
        : "+f"((d)[0]), "+f"((d)[1]), "+f"((d)[2]), "+f"((d)[3]) \
        : "r"(a0), "r"(a1), "r"(a2), "r"(a3), "r"(b0), "r"(b1))

// ---------------------------------------------------------------------------
// QKV projection -> fp16 scratch.
// 256 blocks (4 b x 64 n-chunks of 64), 256 threads, 4 roles (h = tid>>6):
//   h0: q (8 acc, scaled by log2e) + v[ 0:16]
//   h1: k (8 acc)                  + v[16:32]
//   h2: v[32:48]       h3: v[48:64]
// x loaded in explicit 8-wide batches for MLP.
// ---------------------------------------------------------------------------
__global__ __launch_bounds__(256, 2) void qkv_kernel(
    const float* __restrict__ x,
    const float* __restrict__ wq, const float* __restrict__ bq,
    const float* __restrict__ wk, const float* __restrict__ bk,
    const float* __restrict__ wv, const float* __restrict__ bv)
{
    __shared__ float s_wqkT[C * 16];      // [c][0..7]=wq, [c][8..15]=wk
    __shared__ float s_wvT[C * 68];       // [c][o], stride 68
    __shared__ float s_b[2 * CK + C];
    int tid = threadIdx.x;

    for (int i = tid; i < CK * C; i += 256) {
        int o = i >> 6, c = i & 63;
        s_wqkT[c * 16 + o]     = wq[i];
        s_wqkT[c * 16 + 8 + o] = wk[i];
    }
    for (int i = tid; i < C * C; i += 256) {
        int o = i >> 6, c = i & 63;
        s_wvT[c * 68 + o] = wv[i];
    }
    if (tid < CK) s_b[tid] = bq[tid];
    else if (tid < 2 * CK) s_b[tid] = bk[tid - CK];
    else if (tid < 2 * CK + C) s_b[tid] = bv[tid - 2 * CK];
    __syncthreads();

    int b = blockIdx.x >> 6;
    int chunk = blockIdx.x & 63;
    int h = tid >> 6;                 // warp-uniform role
    int n = chunk * 64 + (tid & 63);
    const float* xb = x + (size_t)b * C * N + n;

    bool hasqk = (h < 2);
    int qko = (h == 1) ? 8 : 0;       // q at [0:8], k at [8:16] in s_wqkT rows
    int vc0 = h * 16;

    float a8[CK], av[16];
#pragma unroll
    for (int o = 0; o < CK; o++) a8[o] = 0.f;
#pragma unroll
    for (int o = 0; o < 16; o++) av[o] = 0.f;

    for (int c0 = 0; c0 < C; c0 += 8) {
        float xv[8];
#pragma unroll
        for (int i = 0; i < 8; i++) xv[i] = xb[(size_t)(c0 + i) * N];
#pragma unroll
        for (int i = 0; i < 8; i++) {
            int c = c0 + i;
            float xc = xv[i];
            if (hasqk) {
                const float4* wqk4 = (const float4*)&s_wqkT[c * 16 + qko];
                float4 w0 = wqk4[0], w1 = wqk4[1];
                a8[0] += w0.x * xc; a8[1] += w0.y * xc;
                a8[2] += w0.z * xc; a8[3] += w0.w * xc;
                a8[4] += w1.x * xc; a8[5] += w1.y * xc;
                a8[6] += w1.z * xc; a8[7] += w1.w * xc;
            }
            const float4* wv4 = (const float4*)&s_wvT[c * 68 + vc0];
#pragma unroll
            for (int g = 0; g < 4; g++) {
                float4 w = wv4[g];
                av[4 * g + 0] += w.x * xc;
                av[4 * g + 1] += w.y * xc;
                av[4 * g + 2] += w.z * xc;
                av[4 * g + 3] += w.w * xc;
            }
        }
    }

    if (hasqk) {
        const float* bqk = (h == 1) ? (s_b + CK) : s_b;
        float qscale = (h == 1) ? 1.0f : LOG2E;
        float f[CK];
#pragma unroll
        for (int o = 0; o < CK; o++) f[o] = (a8[o] + bqk[o]) * qscale;
        uint4 pk = make_uint4(pack_h2(f[0], f[1]), pack_h2(f[2], f[3]),
                              pack_h2(f[4], f[5]), pack_h2(f[6], f[7]));
        uint4* dst = (uint4*)(h ? g_k : g_q) + ((size_t)b * N + n);
        *dst = pk;
    }
#pragma unroll
    for (int o = 0; o < 16; o++)
        g_v[((size_t)b * C + vc0 + o) * N + n] =
            __float2half_rn(av[o] + s_b[2 * CK + vc0 + o]);
}

// ---------------------------------------------------------------------------
// Split-K mma.sync fp16 flash attention (unchanged from R11).
// grid (64, 4, 2), 128 threads = 4 warps x 16 queries.
// ---------------------------------------------------------------------------
__global__ __launch_bounds__(128, 4) void attn_kernel()
{
    __shared__ __align__(16) uint32_t k_s[3][TK * 4];
    __shared__ __align__(16) uint32_t v_s[3][TK * 36];

    int tid = threadIdx.x;
    int w = tid >> 5, lane = tid & 31, t = lane & 3, r = lane >> 2;
    int b = blockIdx.y, qbase = blockIdx.x * TQ;
    int sp = blockIdx.z;
    int kt0 = sp * NTS;

    const __half* gq = g_q + (size_t)b * N * CK;
    const __half* gk = g_k + (size_t)b * N * CK;
    const __half* gv = g_v + (size_t)b * C * N;

    uint32_t qa0 = ((const uint32_t*)gq)[(qbase + w * 16 + r) * 4 + t];
    uint32_t qa1 = ((const uint32_t*)gq)[(qbase + w * 16 + r + 8) * 4 + t];

    uint32_t ks_base = smem_u32(k_s);
    uint32_t vs_base = smem_u32(v_s);

    auto stage = [&](int buf, int j0) {
        if (tid < 64)
            cp16(ks_base + buf * (TK * 4 * 4) + tid * 16,
                 gk + (size_t)(j0 + tid) * 8);
#pragma unroll
        for (int i = 0; i < 4; i++) {
            int idx = tid + 128 * i;
            int c = idx >> 3, o = idx & 7;
            cp16(vs_base + buf * (TK * 36 * 4) + c * 144 + o * 16,
                 gv + (size_t)c * N + j0 + o * 8);
        }
        CP_COMMIT();
    };

    stage(0, kt0 * TK);

    float o_[8][4];
#pragma unroll
    for (int n = 0; n < 8; n++)
#pragma unroll
        for (int k = 0; k < 4; k++) o_[n][k] = 0.f;
    float l0 = 0.f, l1 = 0.f, m0 = -1e30f, m1 = -1e30f;

    for (int it = 0; it < NTS; it++) {
        int cur = it % 3;
        if (it + 1 < NTS) {
            stage((it + 1) % 3, (kt0 + it + 1) * TK);
            CP_WAIT1();
        } else {
            CP_WAIT0();
        }
        __syncthreads();

        const uint32_t* kc = k_s[cur];
        const uint32_t* vc = v_s[cur];

        float s[8][4];
#pragma unroll
        for (int jt = 0; jt < 8; jt++) {
            s[jt][0] = 0.f; s[jt][1] = 0.f; s[jt][2] = 0.f; s[jt][3] = 0.f;
            uint32_t kb = kc[(jt * 8 + r) * 4 + t];
            MMA_K8(s[jt], qa0, qa1, kb);
        }

        float tm0 = s[0][0], tm1 = s[0][2];
#pragma unroll
        for (int jt = 0; jt < 8; jt++) {
            tm0 = fmaxf(tm0, fmaxf(s[jt][0], s[jt][1]));
            tm1 = fmaxf(tm1, fmaxf(s[jt][2], s[jt][3]));
        }
        tm0 = fmaxf(tm0, __shfl_xor_sync(0xffffffffu, tm0, 1));
        tm0 = fmaxf(tm0, __shfl_xor_sync(0xffffffffu, tm0, 2));
        tm1 = fmaxf(tm1, __shfl_xor_sync(0xffffffffu, tm1, 1));
        tm1 = fmaxf(tm1, __shfl_xor_sync(0xffffffffu, tm1, 2));
        if (__any_sync(0xffffffffu, (tm0 > m0) | (tm1 > m1))) {
            float mn0 = fmaxf(m0, tm0), mn1 = fmaxf(m1, tm1);
            float al0 = ex2f(m0 - mn0), al1 = ex2f(m1 - mn1);
            l0 *= al0; l1 *= al1;
#pragma unroll
            for (int n = 0; n < 8; n++) {
                o_[n][0] *= al0; o_[n][1] *= al0;
                o_[n][2] *= al1; o_[n][3] *= al1;
            }
            m0 = mn0; m1 = mn1;
        }

        uint32_t pa[4][4];
#pragma unroll
        for (int s4 = 0; s4 < 4; s4++) {
            pa[s4][0] = h2ex2(pack_h2(s[2 * s4][0] - m0,     s[2 * s4][1] - m0));
            pa[s4][1] = h2ex2(pack_h2(s[2 * s4][2] - m1,     s[2 * s4][3] - m1));
            pa[s4][2] = h2ex2(pack_h2(s[2 * s4 + 1][0] - m0, s[2 * s4 + 1][1] - m0));
            pa[s4][3] = h2ex2(pack_h2(s[2 * s4 + 1][2] - m1, s[2 * s4 + 1][3] - m1));
        }

        {
            uint32_t h0 = h2add(h2add(pa[0][0], pa[1][0]), h2add(pa[2][0], pa[3][0]));
            uint32_t h2_ = h2add(h2add(pa[0][2], pa[1][2]), h2add(pa[2][2], pa[3][2]));
            uint32_t hs0 = h2add(h0, h2_);
            uint32_t h1 = h2add(h2add(pa[0][1], pa[1][1]), h2add(pa[2][1], pa[3][1]));
            uint32_t h3 = h2add(h2add(pa[0][3], pa[1][3]), h2add(pa[2][3], pa[3][3]));
            uint32_t hs1 = h2add(h1, h3);
            __half2 v0 = *reinterpret_cast<__half2*>(&hs0);
            __half2 v1 = *reinterpret_cast<__half2*>(&hs1);
            float2 f0 = __half22float2(v0), f1 = __half22float2(v1);
            l0 += f0.x + f0.y;
            l1 += f1.x + f1.y;
        }

#pragma unroll
        for (int s4 = 0; s4 < 4; s4++) {
#pragma unroll
            for (int n = 0; n < 8; n++) {
                uint32_t b0 = vc[(8 * n + r) * 36 + 8 * s4 + t];
                uint32_t b1 = vc[(8 * n + r) * 36 + 8 * s4 + 4 + t];
                MMA_K16(o_[n], pa[s4][0], pa[s4][1], pa[s4][2], pa[s4][3], b0, b1);
            }
        }
        __syncthreads();
    }

    l0 += __shfl_xor_sync(0xffffffffu, l0, 1);
    l0 += __shfl_xor_sync(0xffffffffu, l0, 2);
    l1 += __shfl_xor_sync(0xffffffffu, l1, 1);
    l1 += __shfl_xor_sync(0xffffffffu, l1, 2);

    float* po = g_po + ((size_t)sp * B + b) * C * N;
    int q0 = qbase + w * 16 + r;
#pragma unroll
    for (int n = 0; n < 8; n++) {
        int c = 8 * n + 2 * t;
        size_t i00 = (size_t)c * N + q0;
        size_t i01 = i00 + N;
        po[i00]     = o_[n][0];
        po[i01]     = o_[n][1];
        po[i00 + 8] = o_[n][2];
        po[i01 + 8] = o_[n][3];
    }
    if (t == 0) {
        size_t mi = ((size_t)sp * B + b) * N;
        g_m[mi + q0] = m0;     g_l[mi + q0] = l0;
        g_m[mi + q0 + 8] = m1; g_l[mi + q0 + 8] = l1;
    }
}

// ---------------------------------------------------------------------------
// Combine kernel, float4-vectorized over q.
// grid (N/1024, B, 4): thread handles 4 q x 16 c.
// ---------------------------------------------------------------------------
__global__ __launch_bounds__(256, 1) void combine_kernel(
    const float* __restrict__ x,
    const float* __restrict__ gamma_p,
    float* __restrict__ out)
{
    int q4 = blockIdx.x * 256 + threadIdx.x;   // float4 index over N
    int q = q4 * 4;
    int b = blockIdx.y;
    int c0 = blockIdx.z * 16;

    size_t mi0 = (size_t)b * N + q;
    size_t mi1 = (size_t)(B + b) * N + q;
    float4 m1v = *(const float4*)&g_m[mi0];
    float4 m2v = *(const float4*)&g_m[mi1];
    float4 l1v = *(const float4*)&g_l[mi0];
    float4 l2v = *(const float4*)&g_l[mi1];
    float gm = gamma_p[0];

    float w1[4], w2[4], invl[4];
    {
        float m1a[4] = {m1v.x, m1v.y, m1v.z, m1v.w};
        float m2a[4] = {m2v.x, m2v.y, m2v.z, m2v.w};
        float l1a[4] = {l1v.x, l1v.y, l1v.z, l1v.w};
        float l2a[4] = {l2v.x, l2v.y, l2v.z, l2v.w};
#pragma unroll
        for (int i = 0; i < 4; i++) {
            float M = fmaxf(m1a[i], m2a[i]);
            w1[i] = ex2f(m1a[i] - M);
            w2[i] = ex2f(m2a[i] - M);
            invl[i] = 1.f / (w1[i] * l1a[i] + w2[i] * l2a[i]);
        }
    }

    const float* po1 = g_po + (size_t)b * C * N;
    const float* po2 = g_po + (size_t)(B + b) * C * N;
#pragma unroll 4
    for (int cc = 0; cc < 16; cc++) {
        size_t idx = (size_t)(c0 + cc) * N + q;
        float4 o1 = *(const float4*)&po1[idx];
        float4 o2 = *(const float4*)&po2[idx];
        size_t gidx = (size_t)b * C * N + idx;
        float4 xv = *(const float4*)&x[gidx];
        float4 ov;
        ov.x = gm * (w1[0] * o1.x + w2[0] * o2.x) * invl[0] + xv.x;
        ov.y = gm * (w1[1] * o1.y + w2[1] * o2.y) * invl[1] + xv.y;
        ov.z = gm * (w1[2] * o1.z + w2[2] * o2.z) * invl[2] + xv.z;
        ov.w = gm * (w1[3] * o1.w + w2[3] * o2.w) * invl[3] + xv.w;
        *(float4*)&out[gidx] = ov;
    }
}

// ---------------------------------------------------------------------------
extern "C" void kernel_launch(void* const* d_in, const int* in_sizes, int n_in,
                              void* d_out, int out_size)
{
    const float* x     = (const float*)d_in[0];
    const float* wq    = (const float*)d_in[1];
    const float* bq    = (const float*)d_in[2];
    const float* wk    = (const float*)d_in[3];
    const float* bk    = (const float*)d_in[4];
    const float* wv    = (const float*)d_in[5];
    const float* bv    = (const float*)d_in[6];
    const float* gamma = (const float*)d_in[7];
    float* out = (float*)d_out;

    qkv_kernel<<<256, 256>>>(x, wq, bq, wk, bk, wv, bv);
    dim3 grid(N / TQ, B, SP);
    attn_kernel<<<grid, 128>>>();
    dim3 cg(N / 1024, B, C / 16);
    combine_kernel<<<cg, 256>>>(x, gamma, out);
}

// round 15
// speedup vs baseline: 1.0005x; 1.0005x over previous
#include <cuda_runtime.h>
#include <cuda_fp16.h>
#include <cstdint>

#define DEV_INLINE __device__ __forceinline__

constexpr int B  = 4;
constexpr int C  = 64;
constexpr int CK = 8;
constexpr int N  = 4096;
constexpr int TQ = 64;   // queries per block (4 warps x 16)
constexpr int TK = 64;   // keys per tile
constexpr int NT = N / TK;
constexpr int SP = 2;    // split-K factor
constexpr int NTS = NT / SP;
constexpr float LOG2E = 1.4426950408889634f;

// fp16 scratch:
//   g_q/g_k: [b][n][c]  (8 half = 16B per n)
//   g_v:     [b][c][n]
__device__ __half g_q[B * N * CK];
__device__ __half g_k[B * N * CK];
__device__ __half g_v[B * C * N];
// split-K partials
__device__ float g_po[SP * B * C * N];   // unnormalized O
__device__ float g_m[SP * B * N];
__device__ float g_l[SP * B * N];

DEV_INLINE uint32_t pack_h2(float lo, float hi) {
    uint32_t r;
    asm("cvt.rn.f16x2.f32 %0, %1, %2;" : "=r"(r) : "f"(hi), "f"(lo));
    return r;
}
DEV_INLINE float ex2f(float x) {
    float r; asm("ex2.approx.f32 %0, %1;" : "=f"(r) : "f"(x)); return r;
}
DEV_INLINE uint32_t h2ex2(uint32_t a) {
    uint32_t d; asm("ex2.approx.f16x2 %0, %1;" : "=r"(d) : "r"(a)); return d;
}
DEV_INLINE uint32_t h2add(uint32_t a, uint32_t b) {
    uint32_t d; asm("add.rn.f16x2 %0, %1, %2;" : "=r"(d) : "r"(a), "r"(b)); return d;
}
DEV_INLINE uint32_t smem_u32(const void* p) {
    uint32_t a;
    asm("{ .reg .u64 t; cvta.to.shared.u64 t, %1; cvt.u32.u64 %0, t; }"
        : "=r"(a) : "l"(p));
    return a;
}
DEV_INLINE void cp16(uint32_t dst, const void* src) {
    asm volatile("cp.async.ca.shared.global [%0], [%1], 16;"
                 :: "r"(dst), "l"(src) : "memory");
}
#define CP_COMMIT() asm volatile("cp.async.commit_group;" ::: "memory")
#define CP_WAIT1()  asm volatile("cp.async.wait_group 1;" ::: "memory")
#define CP_WAIT0()  asm volatile("cp.async.wait_group 0;" ::: "memory")

#define MMA_K8(d, a0, a1, b0) \
    asm volatile("mma.sync.aligned.m16n8k8.row.col.f32.f16.f16.f32 " \
        "{%0,%1,%2,%3}, {%4,%5}, {%6}, {%0,%1,%2,%3};" \
        : "+f"((d)[0]), "+f"((d)[1]), "+f"((d)[2]), "+f"((d)[3]) \
        : "r"(a0), "r"(a1), "r"(b0))

#define MMA_K16(d, a0, a1, a2, a3, b0, b1) \
    asm volatile("mma.sync.aligned.m16n8k16.row.col.f32.f16.f16.f32 " \
        "{%0,%1,%2,%3}, {%4,%5,%6,%7}, {%8,%9}, {%0,%1,%2,%3};" \
        : "+f"((d)[0]), "+f"((d)[1]), "+f"((d)[2]), "+f"((d)[3]) \
        : "r"(a0), "r"(a1), "r"(a2), "r"(a3), "r"(b0), "r"(b1))

// ---------------------------------------------------------------------------
// QKV projection -> fp16 scratch.
// 512 blocks (4 b x 128 n-chunks of 32), 128 threads, 4 roles (h = tid>>5):
//   h0: q (8 acc, scaled by log2e) + v[ 0:16]
//   h1: k (8 acc)                  + v[16:32]
//   h2: v[32:48]       h3: v[48:64]
// x loaded in explicit 8-wide batches for MLP. Small CTAs (11.7KB regs) ->
// ~5 resident CTAs/SM for latency hiding.
// ---------------------------------------------------------------------------
__global__ __launch_bounds__(128, 4) void qkv_kernel(
    const float* __restrict__ x,
    const float* __restrict__ wq, const float* __restrict__ bq,
    const float* __restrict__ wk, const float* __restrict__ bk,
    const float* __restrict__ wv, const float* __restrict__ bv)
{
    __shared__ float s_wqkT[C * 16];      // [c][0..7]=wq, [c][8..15]=wk
    __shared__ float s_wvT[C * 68];       // [c][o], stride 68
    __shared__ float s_b[2 * CK + C];
    int tid = threadIdx.x;

    for (int i = tid; i < CK * C; i += 128) {
        int o = i >> 6, c = i & 63;
        s_wqkT[c * 16 + o]     = wq[i];
        s_wqkT[c * 16 + 8 + o] = wk[i];
    }
    for (int i = tid; i < C * C; i += 128) {
        int o = i >> 6, c = i & 63;
        s_wvT[c * 68 + o] = wv[i];
    }
    if (tid < CK) s_b[tid] = bq[tid];
    else if (tid < 2 * CK) s_b[tid] = bk[tid - CK];
    else if (tid < 2 * CK + C) s_b[tid] = bv[tid - 2 * CK];
    __syncthreads();

    int b = blockIdx.x >> 7;
    int chunk = blockIdx.x & 127;
    int h = tid >> 5;                 // warp-uniform role
    int n = chunk * 32 + (tid & 31);
    const float* xb = x + (size_t)b * C * N + n;

    bool hasqk = (h < 2);
    int qko = (h == 1) ? 8 : 0;
    int vc0 = h * 16;

    float a8[CK], av[16];
#pragma unroll
    for (int o = 0; o < CK; o++) a8[o] = 0.f;
#pragma unroll
    for (int o = 0; o < 16; o++) av[o] = 0.f;

    for (int c0 = 0; c0 < C; c0 += 8) {
        float xv[8];
#pragma unroll
        for (int i = 0; i < 8; i++) xv[i] = xb[(size_t)(c0 + i) * N];
#pragma unroll
        for (int i = 0; i < 8; i++) {
            int c = c0 + i;
            float xc = xv[i];
            if (hasqk) {
                const float4* wqk4 = (const float4*)&s_wqkT[c * 16 + qko];
                float4 w0 = wqk4[0], w1 = wqk4[1];
                a8[0] += w0.x * xc; a8[1] += w0.y * xc;
                a8[2] += w0.z * xc; a8[3] += w0.w * xc;
                a8[4] += w1.x * xc; a8[5] += w1.y * xc;
                a8[6] += w1.z * xc; a8[7] += w1.w * xc;
            }
            const float4* wv4 = (const float4*)&s_wvT[c * 68 + vc0];
#pragma unroll
            for (int g = 0; g < 4; g++) {
                float4 w = wv4[g];
                av[4 * g + 0] += w.x * xc;
                av[4 * g + 1] += w.y * xc;
                av[4 * g + 2] += w.z * xc;
                av[4 * g + 3] += w.w * xc;
            }
        }
    }

    if (hasqk) {
        const float* bqk = (h == 1) ? (s_b + CK) : s_b;
        float qscale = (h == 1) ? 1.0f : LOG2E;
        float f[CK];
#pragma unroll
        for (int o = 0; o < CK; o++) f[o] = (a8[o] + bqk[o]) * qscale;
        uint4 pk = make_uint4(pack_h2(f[0], f[1]), pack_h2(f[2], f[3]),
                              pack_h2(f[4], f[5]), pack_h2(f[6], f[7]));
        uint4* dst = (uint4*)(h ? g_k : g_q) + ((size_t)b * N + n);
        *dst = pk;
    }
#pragma unroll
    for (int o = 0; o < 16; o++)
        g_v[((size_t)b * C + vc0 + o) * N + n] =
            __float2half_rn(av[o] + s_b[2 * CK + vc0 + o]);
}

// ---------------------------------------------------------------------------
// Split-K mma.sync fp16 flash attention (unchanged, proven body).
// grid (64, 4, 2), 128 threads = 4 warps x 16 queries.
// ---------------------------------------------------------------------------
__global__ __launch_bounds__(128, 4) void attn_kernel()
{
    __shared__ __align__(16) uint32_t k_s[3][TK * 4];
    __shared__ __align__(16) uint32_t v_s[3][TK * 36];

    int tid = threadIdx.x;
    int w = tid >> 5, lane = tid & 31, t = lane & 3, r = lane >> 2;
    int b = blockIdx.y, qbase = blockIdx.x * TQ;
    int sp = blockIdx.z;
    int kt0 = sp * NTS;

    const __half* gq = g_q + (size_t)b * N * CK;
    const __half* gk = g_k + (size_t)b * N * CK;
    const __half* gv = g_v + (size_t)b * C * N;

    uint32_t qa0 = ((const uint32_t*)gq)[(qbase + w * 16 + r) * 4 + t];
    uint32_t qa1 = ((const uint32_t*)gq)[(qbase + w * 16 + r + 8) * 4 + t];

    uint32_t ks_base = smem_u32(k_s);
    uint32_t vs_base = smem_u32(v_s);

    auto stage = [&](int buf, int j0) {
        if (tid < 64)
            cp16(ks_base + buf * (TK * 4 * 4) + tid * 16,
                 gk + (size_t)(j0 + tid) * 8);
#pragma unroll
        for (int i = 0; i < 4; i++) {
            int idx = tid + 128 * i;
            int c = idx >> 3, o = idx & 7;
            cp16(vs_base + buf * (TK * 36 * 4) + c * 144 + o * 16,
                 gv + (size_t)c * N + j0 + o * 8);
        }
        CP_COMMIT();
    };

    stage(0, kt0 * TK);

    float o_[8][4];
#pragma unroll
    for (int n = 0; n < 8; n++)
#pragma unroll
        for (int k = 0; k < 4; k++) o_[n][k] = 0.f;
    float l0 = 0.f, l1 = 0.f, m0 = -1e30f, m1 = -1e30f;

    for (int it = 0; it < NTS; it++) {
        int cur = it % 3;
        if (it + 1 < NTS) {
            stage((it + 1) % 3, (kt0 + it + 1) * TK);
            CP_WAIT1();
        } else {
            CP_WAIT0();
        }
        __syncthreads();

        const uint32_t* kc = k_s[cur];
        const uint32_t* vc = v_s[cur];

        float s[8][4];
#pragma unroll
        for (int jt = 0; jt < 8; jt++) {
            s[jt][0] = 0.f; s[jt][1] = 0.f; s[jt][2] = 0.f; s[jt][3] = 0.f;
            uint32_t kb = kc[(jt * 8 + r) * 4 + t];
            MMA_K8(s[jt], qa0, qa1, kb);
        }

        float tm0 = s[0][0], tm1 = s[0][2];
#pragma unroll
        for (int jt = 0; jt < 8; jt++) {
            tm0 = fmaxf(tm0, fmaxf(s[jt][0], s[jt][1]));
            tm1 = fmaxf(tm1, fmaxf(s[jt][2], s[jt][3]));
        }
        tm0 = fmaxf(tm0, __shfl_xor_sync(0xffffffffu, tm0, 1));
        tm0 = fmaxf(tm0, __shfl_xor_sync(0xffffffffu, tm0, 2));
        tm1 = fmaxf(tm1, __shfl_xor_sync(0xffffffffu, tm1, 1));
        tm1 = fmaxf(tm1, __shfl_xor_sync(0xffffffffu, tm1, 2));
        if (__any_sync(0xffffffffu, (tm0 > m0) | (tm1 > m1))) {
            float mn0 = fmaxf(m0, tm0), mn1 = fmaxf(m1, tm1);
            float al0 = ex2f(m0 - mn0), al1 = ex2f(m1 - mn1);
            l0 *= al0; l1 *= al1;
#pragma unroll
            for (int n = 0; n < 8; n++) {
                o_[n][0] *= al0; o_[n][1] *= al0;
                o_[n][2] *= al1; o_[n][3] *= al1;
            }
            m0 = mn0; m1 = mn1;
        }

        uint32_t pa[4][4];
#pragma unroll
        for (int s4 = 0; s4 < 4; s4++) {
            pa[s4][0] = h2ex2(pack_h2(s[2 * s4][0] - m0,     s[2 * s4][1] - m0));
            pa[s4][1] = h2ex2(pack_h2(s[2 * s4][2] - m1,     s[2 * s4][3] - m1));
            pa[s4][2] = h2ex2(pack_h2(s[2 * s4 + 1][0] - m0, s[2 * s4 + 1][1] - m0));
            pa[s4][3] = h2ex2(pack_h2(s[2 * s4 + 1][2] - m1, s[2 * s4 + 1][3] - m1));
        }

        {
            uint32_t h0 = h2add(h2add(pa[0][0], pa[1][0]), h2add(pa[2][0], pa[3][0]));
            uint32_t h2_ = h2add(h2add(pa[0][2], pa[1][2]), h2add(pa[2][2], pa[3][2]));
            uint32_t hs0 = h2add(h0, h2_);
            uint32_t h1 = h2add(h2add(pa[0][1], pa[1][1]), h2add(pa[2][1], pa[3][1]));
            uint32_t h3 = h2add(h2add(pa[0][3], pa[1][3]), h2add(pa[2][3], pa[3][3]));
            uint32_t hs1 = h2add(h1, h3);
            __half2 v0 = *reinterpret_cast<__half2*>(&hs0);
            __half2 v1 = *reinterpret_cast<__half2*>(&hs1);
            float2 f0 = __half22float2(v0), f1 = __half22float2(v1);
            l0 += f0.x + f0.y;
            l1 += f1.x + f1.y;
        }

#pragma unroll
        for (int s4 = 0; s4 < 4; s4++) {
#pragma unroll
            for (int n = 0; n < 8; n++) {
                uint32_t b0 = vc[(8 * n + r) * 36 + 8 * s4 + t];
                uint32_t b1 = vc[(8 * n + r) * 36 + 8 * s4 + 4 + t];
                MMA_K16(o_[n], pa[s4][0], pa[s4][1], pa[s4][2], pa[s4][3], b0, b1);
            }
        }
        __syncthreads();
    }

    l0 += __shfl_xor_sync(0xffffffffu, l0, 1);
    l0 += __shfl_xor_sync(0xffffffffu, l0, 2);
    l1 += __shfl_xor_sync(0xffffffffu, l1, 1);
    l1 += __shfl_xor_sync(0xffffffffu, l1, 2);

    float* po = g_po + ((size_t)sp * B + b) * C * N;
    int q0 = qbase + w * 16 + r;
#pragma unroll
    for (int n = 0; n < 8; n++) {
        int c = 8 * n + 2 * t;
        size_t i00 = (size_t)c * N + q0;
        size_t i01 = i00 + N;
        po[i00]     = o_[n][0];
        po[i01]     = o_[n][1];
        po[i00 + 8] = o_[n][2];
        po[i01 + 8] = o_[n][3];
    }
    if (t == 0) {
        size_t mi = ((size_t)sp * B + b) * N;
        g_m[mi + q0] = m0;     g_l[mi + q0] = l0;
        g_m[mi + q0 + 8] = m1; g_l[mi + q0 + 8] = l1;
    }
}

// ---------------------------------------------------------------------------
// Combine kernel: float4 over q AND full-chip grid.
// grid (4, 4, 16) = 256 blocks, 256 threads: thread = 1 float4-q x 4 channels.
// ---------------------------------------------------------------------------
__global__ __launch_bounds__(256, 1) void combine_kernel(
    const float* __restrict__ x,
    const float* __restrict__ gamma_p,
    float* __restrict__ out)
{
    int q4 = blockIdx.x * 256 + threadIdx.x;   // float4 index over N (0..1023)
    int q = q4 * 4;
    int b = blockIdx.y;
    int c0 = blockIdx.z * 4;

    size_t mi0 = (size_t)b * N + q;
    size_t mi1 = (size_t)(B + b) * N + q;
    float4 m1v = *(const float4*)&g_m[mi0];
    float4 m2v = *(const float4*)&g_m[mi1];
    float4 l1v = *(const float4*)&g_l[mi0];
    float4 l2v = *(const float4*)&g_l[mi1];
    float gm = gamma_p[0];

    float w1[4], w2[4], invl[4];
    {
        float m1a[4] = {m1v.x, m1v.y, m1v.z, m1v.w};
        float m2a[4] = {m2v.x, m2v.y, m2v.z, m2v.w};
        float l1a[4] = {l1v.x, l1v.y, l1v.z, l1v.w};
        float l2a[4] = {l2v.x, l2v.y, l2v.z, l2v.w};
#pragma unroll
        for (int i = 0; i < 4; i++) {
            float M = fmaxf(m1a[i], m2a[i]);
            w1[i] = ex2f(m1a[i] - M);
            w2[i] = ex2f(m2a[i] - M);
            invl[i] = 1.f / (w1[i] * l1a[i] + w2[i] * l2a[i]);
        }
    }

    const float* po1 = g_po + (size_t)b * C * N;
    const float* po2 = g_po + (size_t)(B + b) * C * N;
#pragma unroll
    for (int cc = 0; cc < 4; cc++) {
        size_t idx = (size_t)(c0 + cc) * N + q;
        float4 o1 = *(const float4*)&po1[idx];
        float4 o2 = *(const float4*)&po2[idx];
        size_t gidx = (size_t)b * C * N + idx;
        float4 xv = *(const float4*)&x[gidx];
        float4 ov;
        ov.x = gm * (w1[0] * o1.x + w2[0] * o2.x) * invl[0] + xv.x;
        ov.y = gm * (w1[1] * o1.y + w2[1] * o2.y) * invl[1] + xv.y;
        ov.z = gm * (w1[2] * o1.z + w2[2] * o2.z) * invl[2] + xv.z;
        ov.w = gm * (w1[3] * o1.w + w2[3] * o2.w) * invl[3] + xv.w;
        *(float4*)&out[gidx] = ov;
    }
}

// ---------------------------------------------------------------------------
extern "C" void kernel_launch(void* const* d_in, const int* in_sizes, int n_in,
                              void* d_out, int out_size)
{
    const float* x     = (const float*)d_in[0];
    const float* wq    = (const float*)d_in[1];
    const float* bq    = (const float*)d_in[2];
    const float* wk    = (const float*)d_in[3];
    const float* bk    = (const float*)d_in[4];
    const float* wv    = (const float*)d_in[5];
    const float* bv    = (const float*)d_in[6];
    const float* gamma = (const float*)d_in[7];
    float* out = (float*)d_out;

    qkv_kernel<<<512, 128>>>(x, wq, bq, wk, bk, wv, bv);
    dim3 grid(N / TQ, B, SP);
    attn_kernel<<<grid, 128>>>();
    dim3 cg(4, B, 16);
    combine_kernel<<<cg, 256>>>(x, gamma, out);
}